// round 17
// baseline (speedup 1.0000x reference)
#include <cuda_runtime.h>

// 7-DOF forward kinematics — FINAL (best configuration, 10.69-10.75us wall).
//
// Design (each element validated/falsified over 16 measured rounds):
//  * Symbolic reduction: only columns 2,3 of the 25-matrix product are needed
//    -> propagate (point, z-axis) 3-vectors right-to-left; constant 90/180deg
//    rotations folded into (c,s) role/sign swaps of adjacent variable Rz's.
//  * MUFU __sincosf (args all < pi -> fast-path accuracy, rel_err 5.3e-7).
//  * 1 element/thread, 32 regs, 64 warps/SM — every multi-element/ILP variant
//    (4-elem, f32x2 packing) lost warp-level latency hiding and regressed.
//  * Warp-private smem input staging: 56 contiguous LDG.128/warp replace
//    7 stride-7 scalar LDGs (49 L1tex wavefronts -> ~10). Output staging and
//    block-level staging both measured as regressions; stores stay scalar.
//  * Persistent grid NBLK=1184 = 148 SMs x 8 CTAs (exactly one wave), with
//    next chunk's loads issued before current compute.

#define DEG 0.017453292519943295f
#define NBLK 1184
#define NWARPS (NBLK * 8)

__device__ __forceinline__ void fk_math(
    float th0, float th1, float th2, float th3,
    float th4, float th5, float th6,
    float& px, float& py, float& pz, float& vx, float& vy, float& vz)
{
    float r0 = th0 * DEG, r1 = th1 * DEG, r2 = th2 * DEG, r3 = th3 * DEG;
    float r4 = th4 * (-0.5f * DEG);
    float r5 = fmaf(th5, DEG / 4.5f, 10.0f * DEG);
    float r6 = fmaf(th6, DEG / 4.5f, 60.0f * DEG);
    float s0, c0, s1, c1, s2, c2, s3, c3, s4, c4, s5, c5, s6, c6;
    __sincosf(r0, &s0, &c0); __sincosf(r1, &s1, &c1); __sincosf(r2, &s2, &c2);
    __sincosf(r3, &s3, &c3); __sincosf(r4, &s4, &c4); __sincosf(r5, &s5, &c5);
    __sincosf(r6, &s6, &c6);
    float A  = fmaf(6.f, c6, 6.f);
    float Bq = fmaf(6.f, s6, -1.f);
    float p5x = s5 * A + c5 * Bq;
    float p5y = s5 * Bq - c5 * A;
    float s56 = s5 * c6 + c5 * s6;
    float c56 = c5 * c6 - s5 * s6;
    float X = 20.f - p5y, Y = s4 * p5x, vY = s4 * s56;
    float p11x = -c3 * X - s3 * Y;
    float p11y =  s3 * X - c3 * Y;
    float v11x = -c3 * c56 - s3 * vY;
    float v11y =  s3 * c56 - c3 * vY;
    float p12y = c4 * p5x, v12y = c4 * s56;
    float p13x = p11x + 17.5f;
    float p14x = c2 * p13x + s2 * p12y;
    float p14y = c2 * p12y - s2 * p13x;
    float v14x = c2 * v11x + s2 * v12y;
    float v14y = c2 * v12y - s2 * v11x;
    float p16x = p14x + 3.f, p16z = 9.5f - p14y;
    float p17x = c1 * p16x - s1 * p11y;
    float p17y = s1 * p16x + c1 * p11y;
    float v17x = c1 * v14x - s1 * v11y;
    float v17y = s1 * v14x + c1 * v11y;
    float p19y = p17y - 1.5f, p19z = 2.5f - p17x;
    px = -s0 * p16z - c0 * p19y;
    py =  c0 * p16z - s0 * p19y + 5.f;
    pz = p19z + 19.5f;
    vx =  s0 * v14y - c0 * v17y;
    vy = -c0 * v14y - s0 * v17y;
    vz = -v17x;
}

__global__ void __launch_bounds__(256, 8) fk_kernel(
    const float* __restrict__ thetas,   // [B, 7]
    float* __restrict__ out,            // [B*3 points][B*3 vectors]
    int n)
{
    __shared__ float4 stage[8][56];     // per-warp 224 floats

    int warp = threadIdx.x >> 5;
    int lane = threadIdx.x & 31;
    int w = blockIdx.x * 8 + warp;      // global warp id, [0, NWARPS)
    int nchunks = n >> 5;               // full 32-element chunks
    int rem = n & 31;

    // ---- prologue: issue first chunk's loads ----
    int chunk = w;
    float4 f4a, f4b;
    bool have = (chunk < nchunks);
    if (have) {
        const float4* g4 = (const float4*)(thetas + (chunk << 5) * 7);
        f4a = g4[lane];
        if (lane < 24) f4b = g4[32 + lane];
    }

    while (have) {
        int wbase = chunk << 5;
        // stage current chunk
        stage[warp][lane] = f4a;
        if (lane < 24) stage[warp][32 + lane] = f4b;
        __syncwarp();
        const float* t = (const float*)stage[warp] + lane * 7;  // conflict-free
        float th0 = t[0], th1 = t[1], th2 = t[2], th3 = t[3];
        float th4 = t[4], th5 = t[5], th6 = t[6];
        __syncwarp();   // all LDS done before next iter's STS overwrites

        // ---- software pipeline: issue NEXT chunk's loads now ----
        int next = chunk + NWARPS;
        bool have_next = (next < nchunks);
        if (have_next) {
            const float4* g4 = (const float4*)(thetas + (next << 5) * 7);
            f4a = g4[lane];
            if (lane < 24) f4b = g4[32 + lane];
        }

        // compute current chunk (overlaps the in-flight loads)
        float px, py, pz, vx, vy, vz;
        fk_math(th0, th1, th2, th3, th4, th5, th6, px, py, pz, vx, vy, vz);

        int i = wbase + lane;
        int base = i * 3;
        out[base + 0] = px;
        out[base + 1] = py;
        out[base + 2] = pz;
        int vbase = n * 3 + base;
        out[vbase + 0] = vx;
        out[vbase + 1] = vy;
        out[vbase + 2] = vz;

        chunk = next;
        have = have_next;
    }

    // ---- remainder elements (n not divisible by 32) ----
    if (rem && w == 0 && lane < rem) {
        int i = (nchunks << 5) + lane;
        const float* tt = thetas + i * 7;
        float px, py, pz, vx, vy, vz;
        fk_math(tt[0], tt[1], tt[2], tt[3], tt[4], tt[5], tt[6],
                px, py, pz, vx, vy, vz);
        int base = i * 3;
        out[base + 0] = px; out[base + 1] = py; out[base + 2] = pz;
        int vbase = n * 3 + base;
        out[vbase + 0] = vx; out[vbase + 1] = vy; out[vbase + 2] = vz;
    }
}

extern "C" void kernel_launch(void* const* d_in, const int* in_sizes, int n_in,
                              void* d_out, int out_size)
{
    const float* thetas = (const float*)d_in[0];
    float* out = (float*)d_out;
    int n = in_sizes[0] / 7;   // B
    fk_kernel<<<NBLK, 256>>>(thetas, out, n);
}